// round 15
// baseline (speedup 1.0000x reference)
#include <cuda_runtime.h>
#include <math.h>

#define HW 4096
#define BATCH 2

typedef unsigned long long ull;

// Scratch (device globals — no allocation allowed)
__device__ float g_qkv[BATCH * 288 * HW];  // QKV; later reused as out-proj partial slabs
__device__ float g_att[BATCH * 288 * HW];  // channel = head*72 + range*24 + d
__device__ float g_lex[BATCH * 4 * HW];    // per-(b,head,px) boundary l exchange

// ---------------------------------------------------------------------------
// f32x2 helpers
// ---------------------------------------------------------------------------
__device__ __forceinline__ ull pk2(float a) {
    ull r; asm("mov.b64 %0, {%1,%1};" : "=l"(r) : "f"(a)); return r;
}
__device__ __forceinline__ ull pkpair(float lo, float hi) {
    ull r; asm("mov.b64 %0, {%1,%2};" : "=l"(r) : "f"(lo), "f"(hi)); return r;
}
__device__ __forceinline__ ull ffma2(ull a, ull b, ull c) {
    ull d; asm("fma.rn.f32x2 %0, %1, %2, %3;" : "=l"(d) : "l"(a), "l"(b), "l"(c)); return d;
}
__device__ __forceinline__ ull add2(ull a, ull b) {
    ull d; asm("add.rn.f32x2 %0, %1, %2;" : "=l"(d) : "l"(a), "l"(b)); return d;
}
__device__ __forceinline__ void upk(ull v, float& lo, float& hi) {
    asm("mov.b64 {%0,%1}, %2;" : "=f"(lo), "=f"(hi) : "l"(v));
}

// ---------------------------------------------------------------------------
// QKV GEMM, M-SPLIT x2, double-buffered, BK=16:
// BM=48, BN=64, 128 threads, TM=3, TN=8. Direct write + bias.
// z = 0..5: matrix = z>>1 (q/k/v), m-half = z&1. grid (64, BATCH, 6) = 768.
// ---------------------------------------------------------------------------
__global__ __launch_bounds__(128) void gemm_qkv(
    const float* __restrict__ X,
    const float* w0, const float* w1, const float* w2,
    const float* b0, const float* b1, const float* b2,
    float* c0, float* c1, float* c2)
{
    const int mat = blockIdx.z >> 1;
    const int mh  = blockIdx.z & 1;
    const float* __restrict__ W    = ((mat == 0) ? w0 : ((mat == 1) ? w1 : w2)) + (long)mh * 48 * 96;
    const float* __restrict__ bias = ((mat == 0) ? b0 : ((mat == 1) ? b1 : b2)) + mh * 48;
    float* __restrict__ C = ((mat == 0) ? c0 : ((mat == 1) ? c1 : c2))
                            + (long)blockIdx.y * 288 * HW + (long)mh * 48 * HW;
    const float* __restrict__ Xb = X + (long)blockIdx.y * 96 * HW;

    __shared__ float Ws[2][16][50];
    __shared__ float Xs[2][16][64];

    const int tid = threadIdx.x;
    const int tx = tid & 7;
    const int ty = tid >> 3;                 // 0..15, 3 rows each
    const int n0 = blockIdx.x * 64;

    // W tile 48x16 = 192 float4; threads<64 take a second one
    const int wm0 = tid >> 2, wk0 = (tid & 3) * 4;
    const int wm1 = (tid + 128) >> 2, wk1 = (tid & 3) * 4;
    const bool w2nd = tid < 64;
    int xr[2], xc[2];
    #pragma unroll
    for (int i = 0; i < 2; i++) {
        int idx = tid + i * 128;
        xr[i] = idx >> 4;
        xc[i] = (idx & 15) * 4;
    }

    ull acc[3][4] = {};

    // preload tile 0
    {
        float4 w = *(const float4*)&W[(long)wm0 * 96 + wk0];
        Ws[0][wk0 + 0][wm0] = w.x;
        Ws[0][wk0 + 1][wm0] = w.y;
        Ws[0][wk0 + 2][wm0] = w.z;
        Ws[0][wk0 + 3][wm0] = w.w;
        if (w2nd) {
            float4 v = *(const float4*)&W[(long)wm1 * 96 + wk1];
            Ws[0][wk1 + 0][wm1] = v.x;
            Ws[0][wk1 + 1][wm1] = v.y;
            Ws[0][wk1 + 2][wm1] = v.z;
            Ws[0][wk1 + 3][wm1] = v.w;
        }
        #pragma unroll
        for (int i = 0; i < 2; i++)
            *(float4*)&Xs[0][xr[i]][xc[i]] =
                *(const float4*)&Xb[(long)xr[i] * HW + n0 + xc[i]];
    }
    __syncthreads();

    #pragma unroll 1
    for (int t = 0; t < 6; t++) {
        const int cur = t & 1;
        const bool more = (t + 1 < 6);
        const int k1 = (t + 1) * 16;

        float4 wpre0, wpre1, xpre[2];
        if (more) {
            wpre0 = *(const float4*)&W[(long)wm0 * 96 + k1 + wk0];
            if (w2nd) wpre1 = *(const float4*)&W[(long)wm1 * 96 + k1 + wk1];
            #pragma unroll
            for (int i = 0; i < 2; i++)
                xpre[i] = *(const float4*)&Xb[(long)(k1 + xr[i]) * HW + n0 + xc[i]];
        }

        #pragma unroll
        for (int kk = 0; kk < 16; kk++) {
            float a0 = Ws[cur][kk][ty * 3];
            float a1 = Ws[cur][kk][ty * 3 + 1];
            float a2 = Ws[cur][kk][ty * 3 + 2];
            ull ad[3] = {pk2(a0), pk2(a1), pk2(a2)};
            ulonglong2 x0 = *(ulonglong2*)&Xs[cur][kk][tx * 8];
            ulonglong2 x1 = *(ulonglong2*)&Xs[cur][kk][tx * 8 + 4];
            ull bq[4] = {x0.x, x0.y, x1.x, x1.y};
            #pragma unroll
            for (int i = 0; i < 3; i++)
                #pragma unroll
                for (int j = 0; j < 4; j++)
                    acc[i][j] = ffma2(ad[i], bq[j], acc[i][j]);
        }

        if (more) {
            Ws[1 - cur][wk0 + 0][wm0] = wpre0.x;
            Ws[1 - cur][wk0 + 1][wm0] = wpre0.y;
            Ws[1 - cur][wk0 + 2][wm0] = wpre0.z;
            Ws[1 - cur][wk0 + 3][wm0] = wpre0.w;
            if (w2nd) {
                Ws[1 - cur][wk1 + 0][wm1] = wpre1.x;
                Ws[1 - cur][wk1 + 1][wm1] = wpre1.y;
                Ws[1 - cur][wk1 + 2][wm1] = wpre1.z;
                Ws[1 - cur][wk1 + 3][wm1] = wpre1.w;
            }
            #pragma unroll
            for (int i = 0; i < 2; i++)
                *(float4*)&Xs[1 - cur][xr[i]][xc[i]] = xpre[i];
        }
        __syncthreads();
    }

    #pragma unroll
    for (int i = 0; i < 3; i++) {
        int m = ty * 3 + i;
        float bv = bias[m];
        float4 o0, o1;
        upk(acc[i][0], o0.x, o0.y);
        upk(acc[i][1], o0.z, o0.w);
        upk(acc[i][2], o1.x, o1.y);
        upk(acc[i][3], o1.z, o1.w);
        o0.x += bv; o0.y += bv; o0.z += bv; o0.w += bv;
        o1.x += bv; o1.y += bv; o1.z += bv; o1.w += bv;
        float* cp = &C[(long)m * HW + n0 + tx * 8];
        *(float4*)cp = o0;
        *(float4*)(cp + 4) = o1;
    }
}

// ---------------------------------------------------------------------------
// Out-proj GEMM (R13/R10 proven): K-split x2 into partial slabs.
// BM=96, BN=64, BK=16, 128 threads, TM=6, TN=8, double-buffered.
// ---------------------------------------------------------------------------
#define WSTR 102

__global__ __launch_bounds__(128) void gemm_out(
    const float* __restrict__ X,
    const float* __restrict__ W,
    float* c0, float* c1)
{
    const int z = blockIdx.z;
    float* __restrict__ C = ((z == 0) ? c0 : c1) + (long)blockIdx.y * 96 * HW;
    const int kbeg = z * 144;
    const float* __restrict__ Xb = X + (long)blockIdx.y * 288 * HW;

    __shared__ float Ws[2][16][WSTR];
    __shared__ float Xs[2][16][64];

    const int tid = threadIdx.x;
    const int tx = tid & 7;
    const int ty = tid >> 3;
    const int n0 = blockIdx.x * 64;

    int wm[3], wk[3], xr[2], xc[2];
    #pragma unroll
    for (int i = 0; i < 3; i++) {
        int idx = tid + i * 128;
        wm[i] = idx >> 2;
        wk[i] = (idx & 3) * 4;
    }
    #pragma unroll
    for (int i = 0; i < 2; i++) {
        int idx = tid + i * 128;
        xr[i] = idx >> 4;
        xc[i] = (idx & 15) * 4;
    }

    ull acc[6][4] = {};

    #pragma unroll
    for (int i = 0; i < 3; i++) {
        float4 w = *(const float4*)&W[(long)wm[i] * 288 + kbeg + wk[i]];
        Ws[0][wk[i] + 0][wm[i]] = w.x;
        Ws[0][wk[i] + 1][wm[i]] = w.y;
        Ws[0][wk[i] + 2][wm[i]] = w.z;
        Ws[0][wk[i] + 3][wm[i]] = w.w;
    }
    #pragma unroll
    for (int i = 0; i < 2; i++)
        *(float4*)&Xs[0][xr[i]][xc[i]] =
            *(const float4*)&Xb[(long)(kbeg + xr[i]) * HW + n0 + xc[i]];
    __syncthreads();

    #pragma unroll 1
    for (int t = 0; t < 9; t++) {
        const int cur = t & 1;
        const bool more = (t + 1 < 9);
        const int k1 = kbeg + (t + 1) * 16;

        float4 wpre[3], xpre[2];
        if (more) {
            #pragma unroll
            for (int i = 0; i < 3; i++)
                wpre[i] = *(const float4*)&W[(long)wm[i] * 288 + k1 + wk[i]];
            #pragma unroll
            for (int i = 0; i < 2; i++)
                xpre[i] = *(const float4*)&Xb[(long)(k1 + xr[i]) * HW + n0 + xc[i]];
        }

        #pragma unroll
        for (int kk = 0; kk < 16; kk++) {
            float2 a01 = *(float2*)&Ws[cur][kk][ty * 6];
            float2 a23 = *(float2*)&Ws[cur][kk][ty * 6 + 2];
            float2 a45 = *(float2*)&Ws[cur][kk][ty * 6 + 4];
            ull ad[6] = {pk2(a01.x), pk2(a01.y), pk2(a23.x),
                         pk2(a23.y), pk2(a45.x), pk2(a45.y)};
            ulonglong2 x0 = *(ulonglong2*)&Xs[cur][kk][tx * 8];
            ulonglong2 x1 = *(ulonglong2*)&Xs[cur][kk][tx * 8 + 4];
            ull bq[4] = {x0.x, x0.y, x1.x, x1.y};
            #pragma unroll
            for (int i = 0; i < 6; i++)
                #pragma unroll
                for (int j = 0; j < 4; j++)
                    acc[i][j] = ffma2(ad[i], bq[j], acc[i][j]);
        }

        if (more) {
            #pragma unroll
            for (int i = 0; i < 3; i++) {
                Ws[1 - cur][wk[i] + 0][wm[i]] = wpre[i].x;
                Ws[1 - cur][wk[i] + 1][wm[i]] = wpre[i].y;
                Ws[1 - cur][wk[i] + 2][wm[i]] = wpre[i].z;
                Ws[1 - cur][wk[i] + 3][wm[i]] = wpre[i].w;
            }
            #pragma unroll
            for (int i = 0; i < 2; i++)
                *(float4*)&Xs[1 - cur][xr[i]][xc[i]] = xpre[i];
        }
        __syncthreads();
    }

    #pragma unroll
    for (int i = 0; i < 6; i++) {
        int m = ty * 6 + i;
        float4 o0, o1;
        upk(acc[i][0], o0.x, o0.y);
        upk(acc[i][1], o0.z, o0.w);
        upk(acc[i][2], o1.x, o1.y);
        upk(acc[i][3], o1.z, o1.w);
        float* cp = &C[(long)m * HW + n0 + tx * 8];
        *(float4*)cp = o0;
        *(float4*)(cp + 4) = o1;
    }
}

// out = p0 + p1 + bias[m]; 2 float4 per thread (R13 proven)
__global__ __launch_bounds__(256) void finish_out(
    const float* __restrict__ p0, const float* __restrict__ p1,
    const float* __restrict__ bo, float* __restrict__ out)
{
    int t = blockIdx.x * 256 + threadIdx.x;   // < 98304
    float4 a0 = ((const float4*)p0)[t];
    float4 a1 = ((const float4*)p0)[t + 98304];
    float4 b0 = ((const float4*)p1)[t];
    float4 b1 = ((const float4*)p1)[t + 98304];
    int m0 = (t >> 10) % 96;
    int m1 = ((t + 98304) >> 10) % 96;
    float bv0 = bo[m0], bv1 = bo[m1];
    float4 o0, o1;
    o0.x = a0.x + b0.x + bv0; o0.y = a0.y + b0.y + bv0;
    o0.z = a0.z + b0.z + bv0; o0.w = a0.w + b0.w + bv0;
    o1.x = a1.x + b1.x + bv1; o1.y = a1.y + b1.y + bv1;
    o1.z = a1.z + b1.z + bv1; o1.w = a1.w + b1.w + bv1;
    ((float4*)out)[t] = o0;
    ((float4*)out)[t + 98304] = o1;
}

// ---------------------------------------------------------------------------
// Attention v8 (R13 proven, byte-identical): VERTICAL pixel pairs + ROLLING
// accumulator. 8x16 tile; 128 threads = 64 pairs x 2 roles.
// ---------------------------------------------------------------------------
#define PSTR 28
#define HROWS 18
#define HCOLS 26
#define HPX (HROWS * HCOLS)              // 468
#define ATTN_SMEM (2 * HPX * PSTR * 4)   // 104832 B

__global__ __launch_bounds__(128, 2) void attn_kernel()
{
    extern __shared__ float sh[];
    float* Ksh = sh;
    float* Vsh = sh + HPX * PSTR;

    const int head = blockIdx.y;
    const int b = blockIdx.z;
    const int th = (blockIdx.x >> 2) * 8;
    const int tw = (blockIdx.x & 3) * 16;
    const int h0 = th - 5, w0 = tw - 5;

    const float* base = g_qkv + (long)b * 288 * HW;
    const float* Kg = base + (96 + head * 24) * HW;
    const float* Vg = base + (192 + head * 24) * HW;

    const int tid = threadIdx.x;

    {
        int po[4]; int gi[4]; bool ok[4]; int cnt = 0;
        for (int p = tid; p < HPX; p += 128) {
            int py = p / HCOLS, px = p - py * HCOLS;
            int gy = h0 + py, gx = w0 + px;
            po[cnt] = p * PSTR;
            ok[cnt] = ((unsigned)gy < 64u) && ((unsigned)gx < 64u);
            gi[cnt] = ok[cnt] ? (gy * 64 + gx) : 0;
            cnt++;
        }
        #pragma unroll 4
        for (int d = 0; d < 24; d++) {
            long doff = (long)d * HW;
            #pragma unroll
            for (int n = 0; n < 4; n++) {
                if (n < cnt) {
                    float kv = ok[n] ? Kg[doff + gi[n]] : 0.f;
                    float vv = ok[n] ? Vg[doff + gi[n]] : 0.f;
                    Ksh[po[n] + d] = kv;
                    Vsh[po[n] + d] = vv;
                }
            }
        }
    }
    __syncthreads();

    const int role = tid >> 6;            // 0: dy<=0, 1: dy>=1
    const int pid = tid & 63;             // pair id
    const int pr = pid >> 4;              // 0..3 (A row = 2*pr)
    const int px = pid & 15;
    const int rowA = 2 * pr;

    const float* QgA = g_qkv + ((long)b * 288 + head * 24) * HW + (th + rowA) * 64 + (tw + px);
    ull q2A[12], q2B[12];
    #pragma unroll
    for (int j = 0; j < 12; j++) {
        const float sc = 0.2041241452319315f;
        q2A[j] = pkpair(QgA[(long)(2 * j) * HW] * sc,      QgA[(long)(2 * j + 1) * HW] * sc);
        q2B[j] = pkpair(QgA[(long)(2 * j) * HW + 64] * sc, QgA[(long)(2 * j + 1) * HW + 64] * sc);
    }

    ull accA[12] = {}, accB[12] = {}, nxt[12] = {};
    float lA = 0.f, lB = 0.f, lnx = 0.f;
    const int cbase = (rowA + 5) * HCOLS + (px + 5);

    float* A = g_att + ((long)b * 288 + head * 72) * HW + (th + rowA) * 64 + (tw + px);
    const int lidxA = ((b * 4 + head) * HW) + (th + rowA) * 64 + (tw + px);

#define SITE2(POFF, ACA, LA_, ACB, LB_) { \
    const ulonglong2* kp = (const ulonglong2*)(Ksh + (cbase + (POFF)) * PSTR); \
    const ulonglong2* vp = (const ulonglong2*)(Vsh + (cbase + (POFF)) * PSTR); \
    ulonglong2 k0 = kp[0], k1 = kp[1], k2 = kp[2]; \
    ulonglong2 k3 = kp[3], k4 = kp[4], k5 = kp[5]; \
    ull sa = 0ULL, sb = 0ULL, ta = 0ULL, tb = 0ULL; \
    sa = ffma2(q2A[0], k0.x, sa);   sb = ffma2(q2A[1], k0.y, sb); \
    ta = ffma2(q2B[0], k0.x, ta);   tb = ffma2(q2B[1], k0.y, tb); \
    sa = ffma2(q2A[2], k1.x, sa);   sb = ffma2(q2A[3], k1.y, sb); \
    ta = ffma2(q2B[2], k1.x, ta);   tb = ffma2(q2B[3], k1.y, tb); \
    sa = ffma2(q2A[4], k2.x, sa);   sb = ffma2(q2A[5], k2.y, sb); \
    ta = ffma2(q2B[4], k2.x, ta);   tb = ffma2(q2B[5], k2.y, tb); \
    sa = ffma2(q2A[6], k3.x, sa);   sb = ffma2(q2A[7], k3.y, sb); \
    ta = ffma2(q2B[6], k3.x, ta);   tb = ffma2(q2B[7], k3.y, tb); \
    sa = ffma2(q2A[8], k4.x, sa);   sb = ffma2(q2A[9], k4.y, sb); \
    ta = ffma2(q2B[8], k4.x, ta);   tb = ffma2(q2B[9], k4.y, tb); \
    sa = ffma2(q2A[10], k5.x, sa);  sb = ffma2(q2A[11], k5.y, sb); \
    ta = ffma2(q2B[10], k5.x, ta);  tb = ffma2(q2B[11], k5.y, tb); \
    float x0, x1, y0, y1; \
    upk(add2(sa, sb), x0, x1); upk(add2(ta, tb), y0, y1); \
    float eA = __expf(x0 + x1), eB = __expf(y0 + y1); \
    LA_ += eA; LB_ += eB; \
    ull pA = pk2(eA), pB = pk2(eB); \
    ulonglong2 v0 = vp[0], v1 = vp[1], v2 = vp[2]; \
    ulonglong2 v3 = vp[3], v4 = vp[4], v5 = vp[5]; \
    ACA[0] = ffma2(pA, v0.x, ACA[0]);   ACB[0] = ffma2(pB, v0.x, ACB[0]); \
    ACA[1] = ffma2(pA, v0.y, ACA[1]);   ACB[1] = ffma2(pB, v0.y, ACB[1]); \
    ACA[2] = ffma2(pA, v1.x, ACA[2]);   ACB[2] = ffma2(pB, v1.x, ACB[2]); \
    ACA[3] = ffma2(pA, v1.y, ACA[3]);   ACB[3] = ffma2(pB, v1.y, ACB[3]); \
    ACA[4] = ffma2(pA, v2.x, ACA[4]);   ACB[4] = ffma2(pB, v2.x, ACB[4]); \
    ACA[5] = ffma2(pA, v2.y, ACA[5]);   ACB[5] = ffma2(pB, v2.y, ACB[5]); \
    ACA[6] = ffma2(pA, v3.x, ACA[6]);   ACB[6] = ffma2(pB, v3.x, ACB[6]); \
    ACA[7] = ffma2(pA, v3.y, ACA[7]);   ACB[7] = ffma2(pB, v3.y, ACB[7]); \
    ACA[8] = ffma2(pA, v4.x, ACA[8]);   ACB[8] = ffma2(pB, v4.x, ACB[8]); \
    ACA[9] = ffma2(pA, v4.y, ACA[9]);   ACB[9] = ffma2(pB, v4.y, ACB[9]); \
    ACA[10] = ffma2(pA, v5.x, ACA[10]); ACB[10] = ffma2(pB, v5.x, ACB[10]); \
    ACA[11] = ffma2(pA, v5.y, ACA[11]); ACB[11] = ffma2(pB, v5.y, ACB[11]); \
}

#define SITE1(POFF, Q2, AC, L_) { \
    const ulonglong2* kp = (const ulonglong2*)(Ksh + (cbase + (POFF)) * PSTR); \
    const ulonglong2* vp = (const ulonglong2*)(Vsh + (cbase + (POFF)) * PSTR); \
    ulonglong2 k0 = kp[0], k1 = kp[1], k2 = kp[2]; \
    ulonglong2 k3 = kp[3], k4 = kp[4], k5 = kp[5]; \
    ull sa = 0ULL, sb = 0ULL; \
    sa = ffma2(Q2[0], k0.x, sa);  sb = ffma2(Q2[1], k0.y, sb); \
    sa = ffma2(Q2[2], k1.x, sa);  sb = ffma2(Q2[3], k1.y, sb); \
    sa = ffma2(Q2[4], k2.x, sa);  sb = ffma2(Q2[5], k2.y, sb); \
    sa = ffma2(Q2[6], k3.x, sa);  sb = ffma2(Q2[7], k3.y, sb); \
    sa = ffma2(Q2[8], k4.x, sa);  sb = ffma2(Q2[9], k4.y, sb); \
    sa = ffma2(Q2[10], k5.x, sa); sb = ffma2(Q2[11], k5.y, sb); \
    float x0, x1; upk(add2(sa, sb), x0, x1); \
    float e = __expf(x0 + x1); \
    L_ += e; ull pe = pk2(e); \
    ulonglong2 v0 = vp[0], v1 = vp[1], v2 = vp[2]; \
    ulonglong2 v3 = vp[3], v4 = vp[4], v5 = vp[5]; \
    AC[0] = ffma2(pe, v0.x, AC[0]);   AC[1]  = ffma2(pe, v0.y, AC[1]); \
    AC[2] = ffma2(pe, v1.x, AC[2]);   AC[3]  = ffma2(pe, v1.y, AC[3]); \
    AC[4] = ffma2(pe, v2.x, AC[4]);   AC[5]  = ffma2(pe, v2.y, AC[5]); \
    AC[6] = ffma2(pe, v3.x, AC[6]);   AC[7]  = ffma2(pe, v3.y, AC[7]); \
    AC[8] = ffma2(pe, v4.x, AC[8]);   AC[9]  = ffma2(pe, v4.y, AC[9]); \
    AC[10] = ffma2(pe, v5.x, AC[10]); AC[11] = ffma2(pe, v5.y, AC[11]); \
}

#define BOUNDARY(RB) { \
    __syncthreads(); \
    if (role == 1) { \
        _Pragma("unroll") \
        for (int j = 0; j < 12; j++) { \
            float lo, hi; \
            upk(accA[j], lo, hi); \
            A[(long)((RB) + 2 * j) * HW]          = lo; \
            A[(long)((RB) + 2 * j + 1) * HW]      = hi; \
            upk(accB[j], lo, hi); \
            A[(long)((RB) + 2 * j) * HW + 64]     = lo; \
            A[(long)((RB) + 2 * j + 1) * HW + 64] = hi; \
        } \
        g_lex[lidxA]      = lA; \
        g_lex[lidxA + 64] = lB; \
        _Pragma("unroll") \
        for (int j = 0; j < 12; j++) { \
            accA[j] = nxt[j]; nxt[j] = 0ULL; accB[j] = 0ULL; \
        } \
        lA = lnx; lnx = 0.f; lB = 0.f; \
    } \
    __syncthreads(); \
    if (role == 0) { \
        lA += g_lex[lidxA]; \
        lB += g_lex[lidxA + 64]; \
        float rA = __fdividef(1.f, lA); \
        float rB = __fdividef(1.f, lB); \
        _Pragma("unroll") \
        for (int j = 0; j < 12; j++) { \
            float lo, hi; \
            upk(accA[j], lo, hi); \
            lo += A[(long)((RB) + 2 * j) * HW]; \
            hi += A[(long)((RB) + 2 * j + 1) * HW]; \
            accA[j] = pkpair(lo, hi); \
            A[(long)((RB) + 2 * j) * HW]     = lo * rA; \
            A[(long)((RB) + 2 * j + 1) * HW] = hi * rA; \
            upk(accB[j], lo, hi); \
            lo += A[(long)((RB) + 2 * j) * HW + 64]; \
            hi += A[(long)((RB) + 2 * j + 1) * HW + 64]; \
            accB[j] = pkpair(lo, hi); \
            A[(long)((RB) + 2 * j) * HW + 64]     = lo * rB; \
            A[(long)((RB) + 2 * j + 1) * HW + 64] = hi * rB; \
        } \
        _Pragma("unroll") \
        for (int j = 0; j < 12; j++) { \
            accB[j] = add2(accB[j], nxt[j]); nxt[j] = 0ULL; \
        } \
        lB += lnx; lnx = 0.f; \
    } \
}

    // ===== Phase 1 (leading pixel's 7x7 core) =====
    if (role == 0) {
        #pragma unroll 2
        for (int dx = -3; dx <= 3; dx++) { SITE2(-3 * HCOLS + dx, accA, lA, nxt, lnx) }
        #pragma unroll 1
        for (int dy = -2; dy <= 0; dy++) {
            #pragma unroll 2
            for (int dx = -3; dx <= 3; dx++) { SITE2(dy * HCOLS + dx, accA, lA, accB, lB) }
        }
    } else {
        #pragma unroll 1
        for (int dy = 1; dy <= 3; dy++) {
            #pragma unroll 2
            for (int dx = -3; dx <= 3; dx++) { SITE2(dy * HCOLS + dx, accA, lA, accB, lB) }
        }
        #pragma unroll 2
        for (int dx = -3; dx <= 3; dx++) { SITE2(4 * HCOLS + dx, nxt, lnx, accB, lB) }
    }
    BOUNDARY(0)

    // ===== Phase 2 (leading pixel's 9-ring) =====
    if (role == 0) {
        #pragma unroll 2
        for (int dx = -4; dx <= 4; dx++) { SITE2(-4 * HCOLS + dx, accA, lA, nxt, lnx) }
        #pragma unroll 1
        for (int dy = -3; dy <= 0; dy++) {
            SITE2(dy * HCOLS - 4, accA, lA, accB, lB)
            SITE2(dy * HCOLS + 4, accA, lA, accB, lB)
        }
    } else {
        #pragma unroll 2
        for (int dx = -4; dx <= 4; dx++) { SITE2(5 * HCOLS + dx, nxt, lnx, accB, lB) }
        #pragma unroll 1
        for (int dy = 1; dy <= 4; dy++) {
            SITE2(dy * HCOLS - 4, accA, lA, accB, lB)
            SITE2(dy * HCOLS + 4, accA, lA, accB, lB)
        }
    }
    BOUNDARY(24)

    // ===== Phase 3 (leading pixel's 11-ring) =====
    if (role == 0) {
        #pragma unroll 2
        for (int dx = -5; dx <= 5; dx++) { SITE1(-5 * HCOLS + dx, q2A, accA, lA) }
        #pragma unroll 1
        for (int dy = -4; dy <= 0; dy++) {
            SITE2(dy * HCOLS - 5, accA, lA, accB, lB)
            SITE2(dy * HCOLS + 5, accA, lA, accB, lB)
        }
    } else {
        #pragma unroll 2
        for (int dx = -5; dx <= 5; dx++) { SITE1(6 * HCOLS + dx, q2B, accB, lB) }
        #pragma unroll 1
        for (int dy = 1; dy <= 5; dy++) {
            SITE2(dy * HCOLS - 5, accA, lA, accB, lB)
            SITE2(dy * HCOLS + 5, accA, lA, accB, lB)
        }
    }
    BOUNDARY(48)

#undef SITE2
#undef SITE1
#undef BOUNDARY
}

// ---------------------------------------------------------------------------
extern "C" void kernel_launch(void* const* d_in, const int* in_sizes, int n_in,
                              void* d_out, int out_size)
{
    const float* x  = (const float*)d_in[0];
    const float* wq = (const float*)d_in[1];
    const float* bq = (const float*)d_in[2];
    const float* wk = (const float*)d_in[3];
    const float* bk = (const float*)d_in[4];
    const float* wv = (const float*)d_in[5];
    const float* bv = (const float*)d_in[6];
    const float* wo = (const float*)d_in[7];
    const float* bo = (const float*)d_in[8];
    float* out = (float*)d_out;

    float* qkv = nullptr;
    float* att = nullptr;
    cudaGetSymbolAddress((void**)&qkv, g_qkv);
    cudaGetSymbolAddress((void**)&att, g_att);

    cudaFuncSetAttribute(attn_kernel, cudaFuncAttributeMaxDynamicSharedMemorySize, ATTN_SMEM);

    // Fused QKV, M-split x2: grid (64, 2, 6) = 768 CTAs (~5.2/SM)
    gemm_qkv<<<dim3(64, BATCH, 6), 128>>>(
        x, wq, wk, wv, bq, bk, bv,
        qkv, qkv + 96L * HW, qkv + 192L * HW);

    // Multi-range local attention v8 (R13 proven)
    attn_kernel<<<dim3(32, 4, BATCH), 128, ATTN_SMEM>>>();

    // Output projection: K-split x2 into partial slabs (R13 proven)
    float* p0 = qkv;
    float* p1 = qkv + (long)BATCH * 96 * HW;
    gemm_out<<<dim3(64, BATCH, 2), 128>>>(att, wo, p0, p1);

    // out = p0 + p1 + bias (R13 proven)
    finish_out<<<384, 256>>>(p0, p1, bo, out);
}

// round 16
// speedup vs baseline: 1.1920x; 1.1920x over previous
#include <cuda_runtime.h>
#include <math.h>

#define HW 4096
#define BATCH 2

typedef unsigned long long ull;

// Scratch (device globals — no allocation allowed)
__device__ float g_qkv[BATCH * 288 * HW];  // QKV; later reused as out-proj partial slabs
__device__ float g_att[BATCH * 288 * HW];  // channel = head*72 + range*24 + d
__device__ float g_lex[BATCH * 4 * HW];    // per-(b,head,px) boundary l exchange

// ---------------------------------------------------------------------------
// f32x2 helpers
// ---------------------------------------------------------------------------
__device__ __forceinline__ ull pk2(float a) {
    ull r; asm("mov.b64 %0, {%1,%1};" : "=l"(r) : "f"(a)); return r;
}
__device__ __forceinline__ ull pkpair(float lo, float hi) {
    ull r; asm("mov.b64 %0, {%1,%2};" : "=l"(r) : "f"(lo), "f"(hi)); return r;
}
__device__ __forceinline__ ull ffma2(ull a, ull b, ull c) {
    ull d; asm("fma.rn.f32x2 %0, %1, %2, %3;" : "=l"(d) : "l"(a), "l"(b), "l"(c)); return d;
}
__device__ __forceinline__ ull add2(ull a, ull b) {
    ull d; asm("add.rn.f32x2 %0, %1, %2;" : "=l"(d) : "l"(a), "l"(b)); return d;
}
__device__ __forceinline__ void upk(ull v, float& lo, float& hi) {
    asm("mov.b64 {%0,%1}, %2;" : "=f"(lo), "=f"(hi) : "l"(v));
}

#define WSTR 102

// ---------------------------------------------------------------------------
// QKV GEMM, N-SPLIT (BN=32), double-buffered, BK=16:
// BM=96, BN=32, 128 threads, TM=6, TN=4. Direct write + bias.
// grid (128, BATCH, 3) = 768 CTAs (~5.2/SM, ~20 warps/SM).
// X traffic NOT duplicated (disjoint pixel columns); W re-read is L2-resident.
// ---------------------------------------------------------------------------
__global__ __launch_bounds__(128) void gemm_qkv(
    const float* __restrict__ X,
    const float* w0, const float* w1, const float* w2,
    const float* b0, const float* b1, const float* b2,
    float* c0, float* c1, float* c2)
{
    const int z = blockIdx.z;
    const float* __restrict__ W    = (z == 0) ? w0 : ((z == 1) ? w1 : w2);
    const float* __restrict__ bias = (z == 0) ? b0 : ((z == 1) ? b1 : b2);
    float* __restrict__ C = ((z == 0) ? c0 : ((z == 1) ? c1 : c2)) + (long)blockIdx.y * 288 * HW;
    const float* __restrict__ Xb = X + (long)blockIdx.y * 96 * HW;

    __shared__ float Ws[2][16][WSTR];
    __shared__ float Xs[2][16][32];

    const int tid = threadIdx.x;
    const int tx = tid & 7;      // 8 groups x TN=4 = 32 cols
    const int ty = tid >> 3;     // 0..15, 6 rows each
    const int n0 = blockIdx.x * 32;

    // W tile 96x16 = 384 float4: 3 per thread. X tile 16x32 = 128 float4: 1.
    int wm[3], wk[3];
    #pragma unroll
    for (int i = 0; i < 3; i++) {
        int idx = tid + i * 128;
        wm[i] = idx >> 2;
        wk[i] = (idx & 3) * 4;
    }
    const int xr = tid >> 3, xc = (tid & 7) * 4;

    ull acc[6][2] = {};

    // preload tile 0
    #pragma unroll
    for (int i = 0; i < 3; i++) {
        float4 w = *(const float4*)&W[(long)wm[i] * 96 + wk[i]];
        Ws[0][wk[i] + 0][wm[i]] = w.x;
        Ws[0][wk[i] + 1][wm[i]] = w.y;
        Ws[0][wk[i] + 2][wm[i]] = w.z;
        Ws[0][wk[i] + 3][wm[i]] = w.w;
    }
    *(float4*)&Xs[0][xr][xc] = *(const float4*)&Xb[(long)xr * HW + n0 + xc];
    __syncthreads();

    #pragma unroll 1
    for (int t = 0; t < 6; t++) {
        const int cur = t & 1;
        const bool more = (t + 1 < 6);
        const int k1 = (t + 1) * 16;

        float4 wpre[3], xpre;
        if (more) {
            #pragma unroll
            for (int i = 0; i < 3; i++)
                wpre[i] = *(const float4*)&W[(long)wm[i] * 96 + k1 + wk[i]];
            xpre = *(const float4*)&Xb[(long)(k1 + xr) * HW + n0 + xc];
        }

        #pragma unroll
        for (int kk = 0; kk < 16; kk++) {
            float2 a01 = *(float2*)&Ws[cur][kk][ty * 6];
            float2 a23 = *(float2*)&Ws[cur][kk][ty * 6 + 2];
            float2 a45 = *(float2*)&Ws[cur][kk][ty * 6 + 4];
            ull ad[6] = {pk2(a01.x), pk2(a01.y), pk2(a23.x),
                         pk2(a23.y), pk2(a45.x), pk2(a45.y)};
            ulonglong2 x0 = *(ulonglong2*)&Xs[cur][kk][tx * 4];
            ull bq[2] = {x0.x, x0.y};
            #pragma unroll
            for (int i = 0; i < 6; i++)
                #pragma unroll
                for (int j = 0; j < 2; j++)
                    acc[i][j] = ffma2(ad[i], bq[j], acc[i][j]);
        }

        if (more) {
            #pragma unroll
            for (int i = 0; i < 3; i++) {
                Ws[1 - cur][wk[i] + 0][wm[i]] = wpre[i].x;
                Ws[1 - cur][wk[i] + 1][wm[i]] = wpre[i].y;
                Ws[1 - cur][wk[i] + 2][wm[i]] = wpre[i].z;
                Ws[1 - cur][wk[i] + 3][wm[i]] = wpre[i].w;
            }
            *(float4*)&Xs[1 - cur][xr][xc] = xpre;
        }
        __syncthreads();
    }

    #pragma unroll
    for (int i = 0; i < 6; i++) {
        int m = ty * 6 + i;
        float bv = bias[m];
        float4 o0;
        upk(acc[i][0], o0.x, o0.y);
        upk(acc[i][1], o0.z, o0.w);
        o0.x += bv; o0.y += bv; o0.z += bv; o0.w += bv;
        *(float4*)&C[(long)m * HW + n0 + tx * 4] = o0;
    }
}

// ---------------------------------------------------------------------------
// Out-proj GEMM (R13 proven): K-split x2 into partial slabs.
// BM=96, BN=64, BK=16, 128 threads, TM=6, TN=8, double-buffered.
// ---------------------------------------------------------------------------
__global__ __launch_bounds__(128) void gemm_out(
    const float* __restrict__ X,
    const float* __restrict__ W,
    float* c0, float* c1)
{
    const int z = blockIdx.z;
    float* __restrict__ C = ((z == 0) ? c0 : c1) + (long)blockIdx.y * 96 * HW;
    const int kbeg = z * 144;
    const float* __restrict__ Xb = X + (long)blockIdx.y * 288 * HW;

    __shared__ float Ws[2][16][WSTR];
    __shared__ float Xs[2][16][64];

    const int tid = threadIdx.x;
    const int tx = tid & 7;
    const int ty = tid >> 3;
    const int n0 = blockIdx.x * 64;

    int wm[3], wk[3], xr[2], xc[2];
    #pragma unroll
    for (int i = 0; i < 3; i++) {
        int idx = tid + i * 128;
        wm[i] = idx >> 2;
        wk[i] = (idx & 3) * 4;
    }
    #pragma unroll
    for (int i = 0; i < 2; i++) {
        int idx = tid + i * 128;
        xr[i] = idx >> 4;
        xc[i] = (idx & 15) * 4;
    }

    ull acc[6][4] = {};

    #pragma unroll
    for (int i = 0; i < 3; i++) {
        float4 w = *(const float4*)&W[(long)wm[i] * 288 + kbeg + wk[i]];
        Ws[0][wk[i] + 0][wm[i]] = w.x;
        Ws[0][wk[i] + 1][wm[i]] = w.y;
        Ws[0][wk[i] + 2][wm[i]] = w.z;
        Ws[0][wk[i] + 3][wm[i]] = w.w;
    }
    #pragma unroll
    for (int i = 0; i < 2; i++)
        *(float4*)&Xs[0][xr[i]][xc[i]] =
            *(const float4*)&Xb[(long)(kbeg + xr[i]) * HW + n0 + xc[i]];
    __syncthreads();

    #pragma unroll 1
    for (int t = 0; t < 9; t++) {
        const int cur = t & 1;
        const bool more = (t + 1 < 9);
        const int k1 = kbeg + (t + 1) * 16;

        float4 wpre[3], xpre[2];
        if (more) {
            #pragma unroll
            for (int i = 0; i < 3; i++)
                wpre[i] = *(const float4*)&W[(long)wm[i] * 288 + k1 + wk[i]];
            #pragma unroll
            for (int i = 0; i < 2; i++)
                xpre[i] = *(const float4*)&Xb[(long)(k1 + xr[i]) * HW + n0 + xc[i]];
        }

        #pragma unroll
        for (int kk = 0; kk < 16; kk++) {
            float2 a01 = *(float2*)&Ws[cur][kk][ty * 6];
            float2 a23 = *(float2*)&Ws[cur][kk][ty * 6 + 2];
            float2 a45 = *(float2*)&Ws[cur][kk][ty * 6 + 4];
            ull ad[6] = {pk2(a01.x), pk2(a01.y), pk2(a23.x),
                         pk2(a23.y), pk2(a45.x), pk2(a45.y)};
            ulonglong2 x0 = *(ulonglong2*)&Xs[cur][kk][tx * 8];
            ulonglong2 x1 = *(ulonglong2*)&Xs[cur][kk][tx * 8 + 4];
            ull bq[4] = {x0.x, x0.y, x1.x, x1.y};
            #pragma unroll
            for (int i = 0; i < 6; i++)
                #pragma unroll
                for (int j = 0; j < 4; j++)
                    acc[i][j] = ffma2(ad[i], bq[j], acc[i][j]);
        }

        if (more) {
            #pragma unroll
            for (int i = 0; i < 3; i++) {
                Ws[1 - cur][wk[i] + 0][wm[i]] = wpre[i].x;
                Ws[1 - cur][wk[i] + 1][wm[i]] = wpre[i].y;
                Ws[1 - cur][wk[i] + 2][wm[i]] = wpre[i].z;
                Ws[1 - cur][wk[i] + 3][wm[i]] = wpre[i].w;
            }
            #pragma unroll
            for (int i = 0; i < 2; i++)
                *(float4*)&Xs[1 - cur][xr[i]][xc[i]] = xpre[i];
        }
        __syncthreads();
    }

    #pragma unroll
    for (int i = 0; i < 6; i++) {
        int m = ty * 6 + i;
        float4 o0, o1;
        upk(acc[i][0], o0.x, o0.y);
        upk(acc[i][1], o0.z, o0.w);
        upk(acc[i][2], o1.x, o1.y);
        upk(acc[i][3], o1.z, o1.w);
        float* cp = &C[(long)m * HW + n0 + tx * 8];
        *(float4*)cp = o0;
        *(float4*)(cp + 4) = o1;
    }
}

// out = p0 + p1 + bias[m]; 2 float4 per thread (R13 proven)
__global__ __launch_bounds__(256) void finish_out(
    const float* __restrict__ p0, const float* __restrict__ p1,
    const float* __restrict__ bo, float* __restrict__ out)
{
    int t = blockIdx.x * 256 + threadIdx.x;   // < 98304
    float4 a0 = ((const float4*)p0)[t];
    float4 a1 = ((const float4*)p0)[t + 98304];
    float4 b0 = ((const float4*)p1)[t];
    float4 b1 = ((const float4*)p1)[t + 98304];
    int m0 = (t >> 10) % 96;
    int m1 = ((t + 98304) >> 10) % 96;
    float bv0 = bo[m0], bv1 = bo[m1];
    float4 o0, o1;
    o0.x = a0.x + b0.x + bv0; o0.y = a0.y + b0.y + bv0;
    o0.z = a0.z + b0.z + bv0; o0.w = a0.w + b0.w + bv0;
    o1.x = a1.x + b1.x + bv1; o1.y = a1.y + b1.y + bv1;
    o1.z = a1.z + b1.z + bv1; o1.w = a1.w + b1.w + bv1;
    ((float4*)out)[t] = o0;
    ((float4*)out)[t + 98304] = o1;
}

// ---------------------------------------------------------------------------
// Attention v8 (R13 proven, byte-identical): VERTICAL pixel pairs + ROLLING
// accumulator. 8x16 tile; 128 threads = 64 pairs x 2 roles.
// ---------------------------------------------------------------------------
#define PSTR 28
#define HROWS 18
#define HCOLS 26
#define HPX (HROWS * HCOLS)              // 468
#define ATTN_SMEM (2 * HPX * PSTR * 4)   // 104832 B

__global__ __launch_bounds__(128, 2) void attn_kernel()
{
    extern __shared__ float sh[];
    float* Ksh = sh;
    float* Vsh = sh + HPX * PSTR;

    const int head = blockIdx.y;
    const int b = blockIdx.z;
    const int th = (blockIdx.x >> 2) * 8;
    const int tw = (blockIdx.x & 3) * 16;
    const int h0 = th - 5, w0 = tw - 5;

    const float* base = g_qkv + (long)b * 288 * HW;
    const float* Kg = base + (96 + head * 24) * HW;
    const float* Vg = base + (192 + head * 24) * HW;

    const int tid = threadIdx.x;

    {
        int po[4]; int gi[4]; bool ok[4]; int cnt = 0;
        for (int p = tid; p < HPX; p += 128) {
            int py = p / HCOLS, px = p - py * HCOLS;
            int gy = h0 + py, gx = w0 + px;
            po[cnt] = p * PSTR;
            ok[cnt] = ((unsigned)gy < 64u) && ((unsigned)gx < 64u);
            gi[cnt] = ok[cnt] ? (gy * 64 + gx) : 0;
            cnt++;
        }
        #pragma unroll 4
        for (int d = 0; d < 24; d++) {
            long doff = (long)d * HW;
            #pragma unroll
            for (int n = 0; n < 4; n++) {
                if (n < cnt) {
                    float kv = ok[n] ? Kg[doff + gi[n]] : 0.f;
                    float vv = ok[n] ? Vg[doff + gi[n]] : 0.f;
                    Ksh[po[n] + d] = kv;
                    Vsh[po[n] + d] = vv;
                }
            }
        }
    }
    __syncthreads();

    const int role = tid >> 6;            // 0: dy<=0, 1: dy>=1
    const int pid = tid & 63;             // pair id
    const int pr = pid >> 4;              // 0..3 (A row = 2*pr)
    const int px = pid & 15;
    const int rowA = 2 * pr;

    const float* QgA = g_qkv + ((long)b * 288 + head * 24) * HW + (th + rowA) * 64 + (tw + px);
    ull q2A[12], q2B[12];
    #pragma unroll
    for (int j = 0; j < 12; j++) {
        const float sc = 0.2041241452319315f;
        q2A[j] = pkpair(QgA[(long)(2 * j) * HW] * sc,      QgA[(long)(2 * j + 1) * HW] * sc);
        q2B[j] = pkpair(QgA[(long)(2 * j) * HW + 64] * sc, QgA[(long)(2 * j + 1) * HW + 64] * sc);
    }

    ull accA[12] = {}, accB[12] = {}, nxt[12] = {};
    float lA = 0.f, lB = 0.f, lnx = 0.f;
    const int cbase = (rowA + 5) * HCOLS + (px + 5);

    float* A = g_att + ((long)b * 288 + head * 72) * HW + (th + rowA) * 64 + (tw + px);
    const int lidxA = ((b * 4 + head) * HW) + (th + rowA) * 64 + (tw + px);

#define SITE2(POFF, ACA, LA_, ACB, LB_) { \
    const ulonglong2* kp = (const ulonglong2*)(Ksh + (cbase + (POFF)) * PSTR); \
    const ulonglong2* vp = (const ulonglong2*)(Vsh + (cbase + (POFF)) * PSTR); \
    ulonglong2 k0 = kp[0], k1 = kp[1], k2 = kp[2]; \
    ulonglong2 k3 = kp[3], k4 = kp[4], k5 = kp[5]; \
    ull sa = 0ULL, sb = 0ULL, ta = 0ULL, tb = 0ULL; \
    sa = ffma2(q2A[0], k0.x, sa);   sb = ffma2(q2A[1], k0.y, sb); \
    ta = ffma2(q2B[0], k0.x, ta);   tb = ffma2(q2B[1], k0.y, tb); \
    sa = ffma2(q2A[2], k1.x, sa);   sb = ffma2(q2A[3], k1.y, sb); \
    ta = ffma2(q2B[2], k1.x, ta);   tb = ffma2(q2B[3], k1.y, tb); \
    sa = ffma2(q2A[4], k2.x, sa);   sb = ffma2(q2A[5], k2.y, sb); \
    ta = ffma2(q2B[4], k2.x, ta);   tb = ffma2(q2B[5], k2.y, tb); \
    sa = ffma2(q2A[6], k3.x, sa);   sb = ffma2(q2A[7], k3.y, sb); \
    ta = ffma2(q2B[6], k3.x, ta);   tb = ffma2(q2B[7], k3.y, tb); \
    sa = ffma2(q2A[8], k4.x, sa);   sb = ffma2(q2A[9], k4.y, sb); \
    ta = ffma2(q2B[8], k4.x, ta);   tb = ffma2(q2B[9], k4.y, tb); \
    sa = ffma2(q2A[10], k5.x, sa);  sb = ffma2(q2A[11], k5.y, sb); \
    ta = ffma2(q2B[10], k5.x, ta);  tb = ffma2(q2B[11], k5.y, tb); \
    float x0, x1, y0, y1; \
    upk(add2(sa, sb), x0, x1); upk(add2(ta, tb), y0, y1); \
    float eA = __expf(x0 + x1), eB = __expf(y0 + y1); \
    LA_ += eA; LB_ += eB; \
    ull pA = pk2(eA), pB = pk2(eB); \
    ulonglong2 v0 = vp[0], v1 = vp[1], v2 = vp[2]; \
    ulonglong2 v3 = vp[3], v4 = vp[4], v5 = vp[5]; \
    ACA[0] = ffma2(pA, v0.x, ACA[0]);   ACB[0] = ffma2(pB, v0.x, ACB[0]); \
    ACA[1] = ffma2(pA, v0.y, ACA[1]);   ACB[1] = ffma2(pB, v0.y, ACB[1]); \
    ACA[2] = ffma2(pA, v1.x, ACA[2]);   ACB[2] = ffma2(pB, v1.x, ACB[2]); \
    ACA[3] = ffma2(pA, v1.y, ACA[3]);   ACB[3] = ffma2(pB, v1.y, ACB[3]); \
    ACA[4] = ffma2(pA, v2.x, ACA[4]);   ACB[4] = ffma2(pB, v2.x, ACB[4]); \
    ACA[5] = ffma2(pA, v2.y, ACA[5]);   ACB[5] = ffma2(pB, v2.y, ACB[5]); \
    ACA[6] = ffma2(pA, v3.x, ACA[6]);   ACB[6] = ffma2(pB, v3.x, ACB[6]); \
    ACA[7] = ffma2(pA, v3.y, ACA[7]);   ACB[7] = ffma2(pB, v3.y, ACB[7]); \
    ACA[8] = ffma2(pA, v4.x, ACA[8]);   ACB[8] = ffma2(pB, v4.x, ACB[8]); \
    ACA[9] = ffma2(pA, v4.y, ACA[9]);   ACB[9] = ffma2(pB, v4.y, ACB[9]); \
    ACA[10] = ffma2(pA, v5.x, ACA[10]); ACB[10] = ffma2(pB, v5.x, ACB[10]); \
    ACA[11] = ffma2(pA, v5.y, ACA[11]); ACB[11] = ffma2(pB, v5.y, ACB[11]); \
}

#define SITE1(POFF, Q2, AC, L_) { \
    const ulonglong2* kp = (const ulonglong2*)(Ksh + (cbase + (POFF)) * PSTR); \
    const ulonglong2* vp = (const ulonglong2*)(Vsh + (cbase + (POFF)) * PSTR); \
    ulonglong2 k0 = kp[0], k1 = kp[1], k2 = kp[2]; \
    ulonglong2 k3 = kp[3], k4 = kp[4], k5 = kp[5]; \
    ull sa = 0ULL, sb = 0ULL; \
    sa = ffma2(Q2[0], k0.x, sa);  sb = ffma2(Q2[1], k0.y, sb); \
    sa = ffma2(Q2[2], k1.x, sa);  sb = ffma2(Q2[3], k1.y, sb); \
    sa = ffma2(Q2[4], k2.x, sa);  sb = ffma2(Q2[5], k2.y, sb); \
    sa = ffma2(Q2[6], k3.x, sa);  sb = ffma2(Q2[7], k3.y, sb); \
    sa = ffma2(Q2[8], k4.x, sa);  sb = ffma2(Q2[9], k4.y, sb); \
    sa = ffma2(Q2[10], k5.x, sa); sb = ffma2(Q2[11], k5.y, sb); \
    float x0, x1; upk(add2(sa, sb), x0, x1); \
    float e = __expf(x0 + x1); \
    L_ += e; ull pe = pk2(e); \
    ulonglong2 v0 = vp[0], v1 = vp[1], v2 = vp[2]; \
    ulonglong2 v3 = vp[3], v4 = vp[4], v5 = vp[5]; \
    AC[0] = ffma2(pe, v0.x, AC[0]);   AC[1]  = ffma2(pe, v0.y, AC[1]); \
    AC[2] = ffma2(pe, v1.x, AC[2]);   AC[3]  = ffma2(pe, v1.y, AC[3]); \
    AC[4] = ffma2(pe, v2.x, AC[4]);   AC[5]  = ffma2(pe, v2.y, AC[5]); \
    AC[6] = ffma2(pe, v3.x, AC[6]);   AC[7]  = ffma2(pe, v3.y, AC[7]); \
    AC[8] = ffma2(pe, v4.x, AC[8]);   AC[9]  = ffma2(pe, v4.y, AC[9]); \
    AC[10] = ffma2(pe, v5.x, AC[10]); AC[11] = ffma2(pe, v5.y, AC[11]); \
}

#define BOUNDARY(RB) { \
    __syncthreads(); \
    if (role == 1) { \
        _Pragma("unroll") \
        for (int j = 0; j < 12; j++) { \
            float lo, hi; \
            upk(accA[j], lo, hi); \
            A[(long)((RB) + 2 * j) * HW]          = lo; \
            A[(long)((RB) + 2 * j + 1) * HW]      = hi; \
            upk(accB[j], lo, hi); \
            A[(long)((RB) + 2 * j) * HW + 64]     = lo; \
            A[(long)((RB) + 2 * j + 1) * HW + 64] = hi; \
        } \
        g_lex[lidxA]      = lA; \
        g_lex[lidxA + 64] = lB; \
        _Pragma("unroll") \
        for (int j = 0; j < 12; j++) { \
            accA[j] = nxt[j]; nxt[j] = 0ULL; accB[j] = 0ULL; \
        } \
        lA = lnx; lnx = 0.f; lB = 0.f; \
    } \
    __syncthreads(); \
    if (role == 0) { \
        lA += g_lex[lidxA]; \
        lB += g_lex[lidxA + 64]; \
        float rA = __fdividef(1.f, lA); \
        float rB = __fdividef(1.f, lB); \
        _Pragma("unroll") \
        for (int j = 0; j < 12; j++) { \
            float lo, hi; \
            upk(accA[j], lo, hi); \
            lo += A[(long)((RB) + 2 * j) * HW]; \
            hi += A[(long)((RB) + 2 * j + 1) * HW]; \
            accA[j] = pkpair(lo, hi); \
            A[(long)((RB) + 2 * j) * HW]     = lo * rA; \
            A[(long)((RB) + 2 * j + 1) * HW] = hi * rA; \
            upk(accB[j], lo, hi); \
            lo += A[(long)((RB) + 2 * j) * HW + 64]; \
            hi += A[(long)((RB) + 2 * j + 1) * HW + 64]; \
            accB[j] = pkpair(lo, hi); \
            A[(long)((RB) + 2 * j) * HW + 64]     = lo * rB; \
            A[(long)((RB) + 2 * j + 1) * HW + 64] = hi * rB; \
        } \
        _Pragma("unroll") \
        for (int j = 0; j < 12; j++) { \
            accB[j] = add2(accB[j], nxt[j]); nxt[j] = 0ULL; \
        } \
        lB += lnx; lnx = 0.f; \
    } \
}

    // ===== Phase 1 (leading pixel's 7x7 core) =====
    if (role == 0) {
        #pragma unroll 2
        for (int dx = -3; dx <= 3; dx++) { SITE2(-3 * HCOLS + dx, accA, lA, nxt, lnx) }
        #pragma unroll 1
        for (int dy = -2; dy <= 0; dy++) {
            #pragma unroll 2
            for (int dx = -3; dx <= 3; dx++) { SITE2(dy * HCOLS + dx, accA, lA, accB, lB) }
        }
    } else {
        #pragma unroll 1
        for (int dy = 1; dy <= 3; dy++) {
            #pragma unroll 2
            for (int dx = -3; dx <= 3; dx++) { SITE2(dy * HCOLS + dx, accA, lA, accB, lB) }
        }
        #pragma unroll 2
        for (int dx = -3; dx <= 3; dx++) { SITE2(4 * HCOLS + dx, nxt, lnx, accB, lB) }
    }
    BOUNDARY(0)

    // ===== Phase 2 (leading pixel's 9-ring) =====
    if (role == 0) {
        #pragma unroll 2
        for (int dx = -4; dx <= 4; dx++) { SITE2(-4 * HCOLS + dx, accA, lA, nxt, lnx) }
        #pragma unroll 1
        for (int dy = -3; dy <= 0; dy++) {
            SITE2(dy * HCOLS - 4, accA, lA, accB, lB)
            SITE2(dy * HCOLS + 4, accA, lA, accB, lB)
        }
    } else {
        #pragma unroll 2
        for (int dx = -4; dx <= 4; dx++) { SITE2(5 * HCOLS + dx, nxt, lnx, accB, lB) }
        #pragma unroll 1
        for (int dy = 1; dy <= 4; dy++) {
            SITE2(dy * HCOLS - 4, accA, lA, accB, lB)
            SITE2(dy * HCOLS + 4, accA, lA, accB, lB)
        }
    }
    BOUNDARY(24)

    // ===== Phase 3 (leading pixel's 11-ring) =====
    if (role == 0) {
        #pragma unroll 2
        for (int dx = -5; dx <= 5; dx++) { SITE1(-5 * HCOLS + dx, q2A, accA, lA) }
        #pragma unroll 1
        for (int dy = -4; dy <= 0; dy++) {
            SITE2(dy * HCOLS - 5, accA, lA, accB, lB)
            SITE2(dy * HCOLS + 5, accA, lA, accB, lB)
        }
    } else {
        #pragma unroll 2
        for (int dx = -5; dx <= 5; dx++) { SITE1(6 * HCOLS + dx, q2B, accB, lB) }
        #pragma unroll 1
        for (int dy = 1; dy <= 5; dy++) {
            SITE2(dy * HCOLS - 5, accA, lA, accB, lB)
            SITE2(dy * HCOLS + 5, accA, lA, accB, lB)
        }
    }
    BOUNDARY(48)

#undef SITE2
#undef SITE1
#undef BOUNDARY
}

// ---------------------------------------------------------------------------
extern "C" void kernel_launch(void* const* d_in, const int* in_sizes, int n_in,
                              void* d_out, int out_size)
{
    const float* x  = (const float*)d_in[0];
    const float* wq = (const float*)d_in[1];
    const float* bq = (const float*)d_in[2];
    const float* wk = (const float*)d_in[3];
    const float* bk = (const float*)d_in[4];
    const float* wv = (const float*)d_in[5];
    const float* bv = (const float*)d_in[6];
    const float* wo = (const float*)d_in[7];
    const float* bo = (const float*)d_in[8];
    float* out = (float*)d_out;

    float* qkv = nullptr;
    float* att = nullptr;
    cudaGetSymbolAddress((void**)&qkv, g_qkv);
    cudaGetSymbolAddress((void**)&att, g_att);

    cudaFuncSetAttribute(attn_kernel, cudaFuncAttributeMaxDynamicSharedMemorySize, ATTN_SMEM);

    // Fused QKV, N-split (BN=32): grid (128, 2, 3) = 768 CTAs (~20 warps/SM)
    gemm_qkv<<<dim3(128, BATCH, 3), 128>>>(
        x, wq, wk, wv, bq, bk, bv,
        qkv, qkv + 96L * HW, qkv + 192L * HW);

    // Multi-range local attention v8 (R13 proven)
    attn_kernel<<<dim3(32, 4, BATCH), 128, ATTN_SMEM>>>();

    // Output projection: K-split x2 into partial slabs (R13 proven)
    float* p0 = qkv;
    float* p1 = qkv + (long)BATCH * 96 * HW;
    gemm_out<<<dim3(64, BATCH, 2), 128>>>(att, wo, p0, p1);

    // out = p0 + p1 + bias (R13 proven)
    finish_out<<<384, 256>>>(p0, p1, bo, out);
}

// round 17
// speedup vs baseline: 1.2554x; 1.0532x over previous
#include <cuda_runtime.h>
#include <math.h>

#define HW 4096
#define BATCH 2

typedef unsigned long long ull;

// Scratch (device globals — no allocation allowed)
__device__ float g_qkv[BATCH * 288 * HW];  // QKV; later reused as out-proj partial slabs
__device__ float g_att[BATCH * 288 * HW];  // channel = head*72 + range*24 + d
__device__ float g_lex[BATCH * 4 * HW];    // per-(b,head,px) boundary l exchange

// ---------------------------------------------------------------------------
// f32x2 helpers
// ---------------------------------------------------------------------------
__device__ __forceinline__ ull pk2(float a) {
    ull r; asm("mov.b64 %0, {%1,%1};" : "=l"(r) : "f"(a)); return r;
}
__device__ __forceinline__ ull pkpair(float lo, float hi) {
    ull r; asm("mov.b64 %0, {%1,%2};" : "=l"(r) : "f"(lo), "f"(hi)); return r;
}
__device__ __forceinline__ ull ffma2(ull a, ull b, ull c) {
    ull d; asm("fma.rn.f32x2 %0, %1, %2, %3;" : "=l"(d) : "l"(a), "l"(b), "l"(c)); return d;
}
__device__ __forceinline__ ull add2(ull a, ull b) {
    ull d; asm("add.rn.f32x2 %0, %1, %2;" : "=l"(d) : "l"(a), "l"(b)); return d;
}
__device__ __forceinline__ void upk(ull v, float& lo, float& hi) {
    asm("mov.b64 {%0,%1}, %2;" : "=f"(lo), "=f"(hi) : "l"(v));
}

#define WSTR 102

// ---------------------------------------------------------------------------
// GEMM, N-SPLIT (BN=32), double-buffered, BK=16 (R16-proven shape):
// BM=96, BN=32, 128 threads, TM=6, TN=4.
// QKV mode (PARTIAL=false): z selects (W,bias,C), bias added, KTOT=KCHUNK=96.
// Out-proj mode (PARTIAL=true): z selects K-chunk + partial slab, raw store.
// ---------------------------------------------------------------------------
template <int KTOT, int KCHUNK, bool PARTIAL>
__global__ __launch_bounds__(128) void gemm_n32(
    const float* __restrict__ X, long xstride, long cstride,
    const float* w0, const float* w1, const float* w2,
    const float* b0, const float* b1, const float* b2,
    float* c0, float* c1, float* c2)
{
    const int z = blockIdx.z;
    const float* __restrict__ W;
    const float* __restrict__ bias;
    float* __restrict__ C;
    int kbeg;
    if (PARTIAL) {
        W = w0; bias = b0;
        C = (z == 0) ? c0 : c1;
        kbeg = z * KCHUNK;
    } else {
        W    = (z == 0) ? w0 : ((z == 1) ? w1 : w2);
        bias = (z == 0) ? b0 : ((z == 1) ? b1 : b2);
        C    = (z == 0) ? c0 : ((z == 1) ? c1 : c2);
        kbeg = 0;
    }
    C += (long)blockIdx.y * cstride;
    const float* __restrict__ Xb = X + (long)blockIdx.y * xstride;

    __shared__ float Ws[2][16][WSTR];
    __shared__ float Xs[2][16][32];

    const int tid = threadIdx.x;
    const int tx = tid & 7;      // 8 groups x TN=4 = 32 cols
    const int ty = tid >> 3;     // 0..15, 6 rows each
    const int n0 = blockIdx.x * 32;

    int wm[3], wk[3];
    #pragma unroll
    for (int i = 0; i < 3; i++) {
        int idx = tid + i * 128;
        wm[i] = idx >> 2;
        wk[i] = (idx & 3) * 4;
    }
    const int xr = tid >> 3, xc = (tid & 7) * 4;

    ull acc[6][2] = {};

    // preload tile 0
    #pragma unroll
    for (int i = 0; i < 3; i++) {
        float4 w = *(const float4*)&W[(long)wm[i] * KTOT + kbeg + wk[i]];
        Ws[0][wk[i] + 0][wm[i]] = w.x;
        Ws[0][wk[i] + 1][wm[i]] = w.y;
        Ws[0][wk[i] + 2][wm[i]] = w.z;
        Ws[0][wk[i] + 3][wm[i]] = w.w;
    }
    *(float4*)&Xs[0][xr][xc] = *(const float4*)&Xb[(long)(kbeg + xr) * HW + n0 + xc];
    __syncthreads();

    const int NT = KCHUNK / 16;
    #pragma unroll 1
    for (int t = 0; t < NT; t++) {
        const int cur = t & 1;
        const bool more = (t + 1 < NT);
        const int k1 = kbeg + (t + 1) * 16;

        float4 wpre[3], xpre;
        if (more) {
            #pragma unroll
            for (int i = 0; i < 3; i++)
                wpre[i] = *(const float4*)&W[(long)wm[i] * KTOT + k1 + wk[i]];
            xpre = *(const float4*)&Xb[(long)(k1 + xr) * HW + n0 + xc];
        }

        #pragma unroll
        for (int kk = 0; kk < 16; kk++) {
            float2 a01 = *(float2*)&Ws[cur][kk][ty * 6];
            float2 a23 = *(float2*)&Ws[cur][kk][ty * 6 + 2];
            float2 a45 = *(float2*)&Ws[cur][kk][ty * 6 + 4];
            ull ad[6] = {pk2(a01.x), pk2(a01.y), pk2(a23.x),
                         pk2(a23.y), pk2(a45.x), pk2(a45.y)};
            ulonglong2 x0 = *(ulonglong2*)&Xs[cur][kk][tx * 4];
            ull bq[2] = {x0.x, x0.y};
            #pragma unroll
            for (int i = 0; i < 6; i++)
                #pragma unroll
                for (int j = 0; j < 2; j++)
                    acc[i][j] = ffma2(ad[i], bq[j], acc[i][j]);
        }

        if (more) {
            #pragma unroll
            for (int i = 0; i < 3; i++) {
                Ws[1 - cur][wk[i] + 0][wm[i]] = wpre[i].x;
                Ws[1 - cur][wk[i] + 1][wm[i]] = wpre[i].y;
                Ws[1 - cur][wk[i] + 2][wm[i]] = wpre[i].z;
                Ws[1 - cur][wk[i] + 3][wm[i]] = wpre[i].w;
            }
            *(float4*)&Xs[1 - cur][xr][xc] = xpre;
        }
        __syncthreads();
    }

    #pragma unroll
    for (int i = 0; i < 6; i++) {
        int m = ty * 6 + i;
        float bv = PARTIAL ? 0.f : bias[m];
        float4 o0;
        upk(acc[i][0], o0.x, o0.y);
        upk(acc[i][1], o0.z, o0.w);
        o0.x += bv; o0.y += bv; o0.z += bv; o0.w += bv;
        *(float4*)&C[(long)m * HW + n0 + tx * 4] = o0;
    }
}

// out = p0 + p1 + bias[m]; 2 float4 per thread (R13 proven)
__global__ __launch_bounds__(256) void finish_out(
    const float* __restrict__ p0, const float* __restrict__ p1,
    const float* __restrict__ bo, float* __restrict__ out)
{
    int t = blockIdx.x * 256 + threadIdx.x;   // < 98304
    float4 a0 = ((const float4*)p0)[t];
    float4 a1 = ((const float4*)p0)[t + 98304];
    float4 b0 = ((const float4*)p1)[t];
    float4 b1 = ((const float4*)p1)[t + 98304];
    int m0 = (t >> 10) % 96;
    int m1 = ((t + 98304) >> 10) % 96;
    float bv0 = bo[m0], bv1 = bo[m1];
    float4 o0, o1;
    o0.x = a0.x + b0.x + bv0; o0.y = a0.y + b0.y + bv0;
    o0.z = a0.z + b0.z + bv0; o0.w = a0.w + b0.w + bv0;
    o1.x = a1.x + b1.x + bv1; o1.y = a1.y + b1.y + bv1;
    o1.z = a1.z + b1.z + bv1; o1.w = a1.w + b1.w + bv1;
    ((float4*)out)[t] = o0;
    ((float4*)out)[t + 98304] = o1;
}

// ---------------------------------------------------------------------------
// Attention v8 (R13 proven, byte-identical): VERTICAL pixel pairs + ROLLING
// accumulator. 8x16 tile; 128 threads = 64 pairs x 2 roles.
// ---------------------------------------------------------------------------
#define PSTR 28
#define HROWS 18
#define HCOLS 26
#define HPX (HROWS * HCOLS)              // 468
#define ATTN_SMEM (2 * HPX * PSTR * 4)   // 104832 B

__global__ __launch_bounds__(128, 2) void attn_kernel()
{
    extern __shared__ float sh[];
    float* Ksh = sh;
    float* Vsh = sh + HPX * PSTR;

    const int head = blockIdx.y;
    const int b = blockIdx.z;
    const int th = (blockIdx.x >> 2) * 8;
    const int tw = (blockIdx.x & 3) * 16;
    const int h0 = th - 5, w0 = tw - 5;

    const float* base = g_qkv + (long)b * 288 * HW;
    const float* Kg = base + (96 + head * 24) * HW;
    const float* Vg = base + (192 + head * 24) * HW;

    const int tid = threadIdx.x;

    {
        int po[4]; int gi[4]; bool ok[4]; int cnt = 0;
        for (int p = tid; p < HPX; p += 128) {
            int py = p / HCOLS, px = p - py * HCOLS;
            int gy = h0 + py, gx = w0 + px;
            po[cnt] = p * PSTR;
            ok[cnt] = ((unsigned)gy < 64u) && ((unsigned)gx < 64u);
            gi[cnt] = ok[cnt] ? (gy * 64 + gx) : 0;
            cnt++;
        }
        #pragma unroll 4
        for (int d = 0; d < 24; d++) {
            long doff = (long)d * HW;
            #pragma unroll
            for (int n = 0; n < 4; n++) {
                if (n < cnt) {
                    float kv = ok[n] ? Kg[doff + gi[n]] : 0.f;
                    float vv = ok[n] ? Vg[doff + gi[n]] : 0.f;
                    Ksh[po[n] + d] = kv;
                    Vsh[po[n] + d] = vv;
                }
            }
        }
    }
    __syncthreads();

    const int role = tid >> 6;            // 0: dy<=0, 1: dy>=1
    const int pid = tid & 63;             // pair id
    const int pr = pid >> 4;              // 0..3 (A row = 2*pr)
    const int px = pid & 15;
    const int rowA = 2 * pr;

    const float* QgA = g_qkv + ((long)b * 288 + head * 24) * HW + (th + rowA) * 64 + (tw + px);
    ull q2A[12], q2B[12];
    #pragma unroll
    for (int j = 0; j < 12; j++) {
        const float sc = 0.2041241452319315f;
        q2A[j] = pkpair(QgA[(long)(2 * j) * HW] * sc,      QgA[(long)(2 * j + 1) * HW] * sc);
        q2B[j] = pkpair(QgA[(long)(2 * j) * HW + 64] * sc, QgA[(long)(2 * j + 1) * HW + 64] * sc);
    }

    ull accA[12] = {}, accB[12] = {}, nxt[12] = {};
    float lA = 0.f, lB = 0.f, lnx = 0.f;
    const int cbase = (rowA + 5) * HCOLS + (px + 5);

    float* A = g_att + ((long)b * 288 + head * 72) * HW + (th + rowA) * 64 + (tw + px);
    const int lidxA = ((b * 4 + head) * HW) + (th + rowA) * 64 + (tw + px);

#define SITE2(POFF, ACA, LA_, ACB, LB_) { \
    const ulonglong2* kp = (const ulonglong2*)(Ksh + (cbase + (POFF)) * PSTR); \
    const ulonglong2* vp = (const ulonglong2*)(Vsh + (cbase + (POFF)) * PSTR); \
    ulonglong2 k0 = kp[0], k1 = kp[1], k2 = kp[2]; \
    ulonglong2 k3 = kp[3], k4 = kp[4], k5 = kp[5]; \
    ull sa = 0ULL, sb = 0ULL, ta = 0ULL, tb = 0ULL; \
    sa = ffma2(q2A[0], k0.x, sa);   sb = ffma2(q2A[1], k0.y, sb); \
    ta = ffma2(q2B[0], k0.x, ta);   tb = ffma2(q2B[1], k0.y, tb); \
    sa = ffma2(q2A[2], k1.x, sa);   sb = ffma2(q2A[3], k1.y, sb); \
    ta = ffma2(q2B[2], k1.x, ta);   tb = ffma2(q2B[3], k1.y, tb); \
    sa = ffma2(q2A[4], k2.x, sa);   sb = ffma2(q2A[5], k2.y, sb); \
    ta = ffma2(q2B[4], k2.x, ta);   tb = ffma2(q2B[5], k2.y, tb); \
    sa = ffma2(q2A[6], k3.x, sa);   sb = ffma2(q2A[7], k3.y, sb); \
    ta = ffma2(q2B[6], k3.x, ta);   tb = ffma2(q2B[7], k3.y, tb); \
    sa = ffma2(q2A[8], k4.x, sa);   sb = ffma2(q2A[9], k4.y, sb); \
    ta = ffma2(q2B[8], k4.x, ta);   tb = ffma2(q2B[9], k4.y, tb); \
    sa = ffma2(q2A[10], k5.x, sa);  sb = ffma2(q2A[11], k5.y, sb); \
    ta = ffma2(q2B[10], k5.x, ta);  tb = ffma2(q2B[11], k5.y, tb); \
    float x0, x1, y0, y1; \
    upk(add2(sa, sb), x0, x1); upk(add2(ta, tb), y0, y1); \
    float eA = __expf(x0 + x1), eB = __expf(y0 + y1); \
    LA_ += eA; LB_ += eB; \
    ull pA = pk2(eA), pB = pk2(eB); \
    ulonglong2 v0 = vp[0], v1 = vp[1], v2 = vp[2]; \
    ulonglong2 v3 = vp[3], v4 = vp[4], v5 = vp[5]; \
    ACA[0] = ffma2(pA, v0.x, ACA[0]);   ACB[0] = ffma2(pB, v0.x, ACB[0]); \
    ACA[1] = ffma2(pA, v0.y, ACA[1]);   ACB[1] = ffma2(pB, v0.y, ACB[1]); \
    ACA[2] = ffma2(pA, v1.x, ACA[2]);   ACB[2] = ffma2(pB, v1.x, ACB[2]); \
    ACA[3] = ffma2(pA, v1.y, ACA[3]);   ACB[3] = ffma2(pB, v1.y, ACB[3]); \
    ACA[4] = ffma2(pA, v2.x, ACA[4]);   ACB[4] = ffma2(pB, v2.x, ACB[4]); \
    ACA[5] = ffma2(pA, v2.y, ACA[5]);   ACB[5] = ffma2(pB, v2.y, ACB[5]); \
    ACA[6] = ffma2(pA, v3.x, ACA[6]);   ACB[6] = ffma2(pB, v3.x, ACB[6]); \
    ACA[7] = ffma2(pA, v3.y, ACA[7]);   ACB[7] = ffma2(pB, v3.y, ACB[7]); \
    ACA[8] = ffma2(pA, v4.x, ACA[8]);   ACB[8] = ffma2(pB, v4.x, ACB[8]); \
    ACA[9] = ffma2(pA, v4.y, ACA[9]);   ACB[9] = ffma2(pB, v4.y, ACB[9]); \
    ACA[10] = ffma2(pA, v5.x, ACA[10]); ACB[10] = ffma2(pB, v5.x, ACB[10]); \
    ACA[11] = ffma2(pA, v5.y, ACA[11]); ACB[11] = ffma2(pB, v5.y, ACB[11]); \
}

#define SITE1(POFF, Q2, AC, L_) { \
    const ulonglong2* kp = (const ulonglong2*)(Ksh + (cbase + (POFF)) * PSTR); \
    const ulonglong2* vp = (const ulonglong2*)(Vsh + (cbase + (POFF)) * PSTR); \
    ulonglong2 k0 = kp[0], k1 = kp[1], k2 = kp[2]; \
    ulonglong2 k3 = kp[3], k4 = kp[4], k5 = kp[5]; \
    ull sa = 0ULL, sb = 0ULL; \
    sa = ffma2(Q2[0], k0.x, sa);  sb = ffma2(Q2[1], k0.y, sb); \
    sa = ffma2(Q2[2], k1.x, sa);  sb = ffma2(Q2[3], k1.y, sb); \
    sa = ffma2(Q2[4], k2.x, sa);  sb = ffma2(Q2[5], k2.y, sb); \
    sa = ffma2(Q2[6], k3.x, sa);  sb = ffma2(Q2[7], k3.y, sb); \
    sa = ffma2(Q2[8], k4.x, sa);  sb = ffma2(Q2[9], k4.y, sb); \
    sa = ffma2(Q2[10], k5.x, sa); sb = ffma2(Q2[11], k5.y, sb); \
    float x0, x1; upk(add2(sa, sb), x0, x1); \
    float e = __expf(x0 + x1); \
    L_ += e; ull pe = pk2(e); \
    ulonglong2 v0 = vp[0], v1 = vp[1], v2 = vp[2]; \
    ulonglong2 v3 = vp[3], v4 = vp[4], v5 = vp[5]; \
    AC[0] = ffma2(pe, v0.x, AC[0]);   AC[1]  = ffma2(pe, v0.y, AC[1]); \
    AC[2] = ffma2(pe, v1.x, AC[2]);   AC[3]  = ffma2(pe, v1.y, AC[3]); \
    AC[4] = ffma2(pe, v2.x, AC[4]);   AC[5]  = ffma2(pe, v2.y, AC[5]); \
    AC[6] = ffma2(pe, v3.x, AC[6]);   AC[7]  = ffma2(pe, v3.y, AC[7]); \
    AC[8] = ffma2(pe, v4.x, AC[8]);   AC[9]  = ffma2(pe, v4.y, AC[9]); \
    AC[10] = ffma2(pe, v5.x, AC[10]); AC[11] = ffma2(pe, v5.y, AC[11]); \
}

#define BOUNDARY(RB) { \
    __syncthreads(); \
    if (role == 1) { \
        _Pragma("unroll") \
        for (int j = 0; j < 12; j++) { \
            float lo, hi; \
            upk(accA[j], lo, hi); \
            A[(long)((RB) + 2 * j) * HW]          = lo; \
            A[(long)((RB) + 2 * j + 1) * HW]      = hi; \
            upk(accB[j], lo, hi); \
            A[(long)((RB) + 2 * j) * HW + 64]     = lo; \
            A[(long)((RB) + 2 * j + 1) * HW + 64] = hi; \
        } \
        g_lex[lidxA]      = lA; \
        g_lex[lidxA + 64] = lB; \
        _Pragma("unroll") \
        for (int j = 0; j < 12; j++) { \
            accA[j] = nxt[j]; nxt[j] = 0ULL; accB[j] = 0ULL; \
        } \
        lA = lnx; lnx = 0.f; lB = 0.f; \
    } \
    __syncthreads(); \
    if (role == 0) { \
        lA += g_lex[lidxA]; \
        lB += g_lex[lidxA + 64]; \
        float rA = __fdividef(1.f, lA); \
        float rB = __fdividef(1.f, lB); \
        _Pragma("unroll") \
        for (int j = 0; j < 12; j++) { \
            float lo, hi; \
            upk(accA[j], lo, hi); \
            lo += A[(long)((RB) + 2 * j) * HW]; \
            hi += A[(long)((RB) + 2 * j + 1) * HW]; \
            accA[j] = pkpair(lo, hi); \
            A[(long)((RB) + 2 * j) * HW]     = lo * rA; \
            A[(long)((RB) + 2 * j + 1) * HW] = hi * rA; \
            upk(accB[j], lo, hi); \
            lo += A[(long)((RB) + 2 * j) * HW + 64]; \
            hi += A[(long)((RB) + 2 * j + 1) * HW + 64]; \
            accB[j] = pkpair(lo, hi); \
            A[(long)((RB) + 2 * j) * HW + 64]     = lo * rB; \
            A[(long)((RB) + 2 * j + 1) * HW + 64] = hi * rB; \
        } \
        _Pragma("unroll") \
        for (int j = 0; j < 12; j++) { \
            accB[j] = add2(accB[j], nxt[j]); nxt[j] = 0ULL; \
        } \
        lB += lnx; lnx = 0.f; \
    } \
}

    // ===== Phase 1 (leading pixel's 7x7 core) =====
    if (role == 0) {
        #pragma unroll 2
        for (int dx = -3; dx <= 3; dx++) { SITE2(-3 * HCOLS + dx, accA, lA, nxt, lnx) }
        #pragma unroll 1
        for (int dy = -2; dy <= 0; dy++) {
            #pragma unroll 2
            for (int dx = -3; dx <= 3; dx++) { SITE2(dy * HCOLS + dx, accA, lA, accB, lB) }
        }
    } else {
        #pragma unroll 1
        for (int dy = 1; dy <= 3; dy++) {
            #pragma unroll 2
            for (int dx = -3; dx <= 3; dx++) { SITE2(dy * HCOLS + dx, accA, lA, accB, lB) }
        }
        #pragma unroll 2
        for (int dx = -3; dx <= 3; dx++) { SITE2(4 * HCOLS + dx, nxt, lnx, accB, lB) }
    }
    BOUNDARY(0)

    // ===== Phase 2 (leading pixel's 9-ring) =====
    if (role == 0) {
        #pragma unroll 2
        for (int dx = -4; dx <= 4; dx++) { SITE2(-4 * HCOLS + dx, accA, lA, nxt, lnx) }
        #pragma unroll 1
        for (int dy = -3; dy <= 0; dy++) {
            SITE2(dy * HCOLS - 4, accA, lA, accB, lB)
            SITE2(dy * HCOLS + 4, accA, lA, accB, lB)
        }
    } else {
        #pragma unroll 2
        for (int dx = -4; dx <= 4; dx++) { SITE2(5 * HCOLS + dx, nxt, lnx, accB, lB) }
        #pragma unroll 1
        for (int dy = 1; dy <= 4; dy++) {
            SITE2(dy * HCOLS - 4, accA, lA, accB, lB)
            SITE2(dy * HCOLS + 4, accA, lA, accB, lB)
        }
    }
    BOUNDARY(24)

    // ===== Phase 3 (leading pixel's 11-ring) =====
    if (role == 0) {
        #pragma unroll 2
        for (int dx = -5; dx <= 5; dx++) { SITE1(-5 * HCOLS + dx, q2A, accA, lA) }
        #pragma unroll 1
        for (int dy = -4; dy <= 0; dy++) {
            SITE2(dy * HCOLS - 5, accA, lA, accB, lB)
            SITE2(dy * HCOLS + 5, accA, lA, accB, lB)
        }
    } else {
        #pragma unroll 2
        for (int dx = -5; dx <= 5; dx++) { SITE1(6 * HCOLS + dx, q2B, accB, lB) }
        #pragma unroll 1
        for (int dy = 1; dy <= 5; dy++) {
            SITE2(dy * HCOLS - 5, accA, lA, accB, lB)
            SITE2(dy * HCOLS + 5, accA, lA, accB, lB)
        }
    }
    BOUNDARY(48)

#undef SITE2
#undef SITE1
#undef BOUNDARY
}

// ---------------------------------------------------------------------------
extern "C" void kernel_launch(void* const* d_in, const int* in_sizes, int n_in,
                              void* d_out, int out_size)
{
    const float* x  = (const float*)d_in[0];
    const float* wq = (const float*)d_in[1];
    const float* bq = (const float*)d_in[2];
    const float* wk = (const float*)d_in[3];
    const float* bk = (const float*)d_in[4];
    const float* wv = (const float*)d_in[5];
    const float* bv = (const float*)d_in[6];
    const float* wo = (const float*)d_in[7];
    const float* bo = (const float*)d_in[8];
    float* out = (float*)d_out;

    float* qkv = nullptr;
    float* att = nullptr;
    cudaGetSymbolAddress((void**)&qkv, g_qkv);
    cudaGetSymbolAddress((void**)&att, g_att);

    cudaFuncSetAttribute(attn_kernel, cudaFuncAttributeMaxDynamicSharedMemorySize, ATTN_SMEM);

    // Fused QKV, N-split (BN=32): grid (128, 2, 3) = 768 CTAs (R16 proven)
    gemm_n32<96, 96, false><<<dim3(128, BATCH, 3), 128>>>(
        x, 96L * HW, 288L * HW,
        wq, wk, wv, bq, bk, bv,
        qkv, qkv + 96L * HW, qkv + 192L * HW);

    // Multi-range local attention v8 (R13 proven)
    attn_kernel<<<dim3(32, 4, BATCH), 128, ATTN_SMEM>>>();

    // Output projection: K-split x2 AND N-split (BN=32): 512 CTAs
    float* p0 = qkv;
    float* p1 = qkv + (long)BATCH * 96 * HW;
    gemm_n32<288, 144, true><<<dim3(128, BATCH, 2), 128>>>(
        att, 288L * HW, 96L * HW,
        wo, wo, wo, bo, bo, bo,
        p0, p1, p1);

    // out = p0 + p1 + bias (R13 proven)
    finish_out<<<384, 256>>>(p0, p1, bo, out);
}